// round 1
// baseline (speedup 1.0000x reference)
#include <cuda_runtime.h>
#include <math.h>

// ---------------- problem constants ----------------
#define BATCH 2048
#define DIMD  1024
#define UNITS 1024
#define MEMS  8
#define SLOTS 9                 // M + 1
#define ROWS  (BATCH*SLOTS)     // 18432
#define HEADS 16
#define DH    64
#define GROWS (BATCH*MEMS)      // 16384
#define LN_EPS 1e-5f

// ---------------- scratch (device globals; no allocation allowed) ----------
__device__ float g_memplus[ROWS*UNITS];      // [B,9,U]
__device__ float g_qkv[ROWS*3*UNITS];        // [B,9,3U]
__device__ float g_att[ROWS*UNITS];          // attention output
__device__ float g_h[ROWS*UNITS];            // LN1 output
__device__ float g_t[ROWS*UNITS];            // gelu(h@w1+b)
__device__ float g_hm[ROWS*UNITS];           // h + mlp2
__device__ float g_h2[ROWS*UNITS];           // LN2 output
__device__ float g_g0[BATCH*2*UNITS];        // inputs@gate_kernel
__device__ float g_g1[GROWS*2*UNITS];        // memory@recurrent_kernel + rbias
__device__ float g_tab[17*UNITS];            // rel-pos sinusoid table
__device__ float g_rel[17*UNITS];            // tab @ rel_kernel

// ---------------- SGEMM: C[M,N] = A[M,K] @ B[K,N] (+bias)(+gelu|+res) -----
#define BM 128
#define BN 128
#define BKK 8
#define TM 8
#define TN 8

#define EPI_NONE 0
#define EPI_BIAS 1
#define EPI_GELU 2
#define EPI_RES  3

__device__ __forceinline__ float gelu_tanh(float x) {
    const float c0 = 0.7978845608028654f;   // sqrt(2/pi)
    const float c1 = 0.044715f;
    return 0.5f * x * (1.0f + tanhf(c0 * (x + c1 * x * x * x)));
}

template<int EPI>
__global__ void __launch_bounds__(256)
sgemm_kernel(const float* __restrict__ A, int lda,
             const float* __restrict__ B, int ldb,
             const float* __restrict__ bias,
             const float* __restrict__ res, int ldres,
             float* __restrict__ C, int ldc,
             int M, int N, int K)
{
    __shared__ float As[BKK][BM];
    __shared__ float Bs[BKK][BN];

    const int tid = threadIdx.x;
    const int bm = blockIdx.y * BM;
    const int bn = blockIdx.x * BN;

    const int a_row = tid >> 1;            // 0..127
    const int a_col = (tid & 1) * 4;       // 0 or 4
    const int b_row = tid >> 5;            // 0..7
    const int b_col = (tid & 31) * 4;      // 0..124

    const int tx = tid & 15;               // 0..15
    const int ty = tid >> 4;               // 0..15

    float acc[TM][TN];
    #pragma unroll
    for (int i = 0; i < TM; i++)
        #pragma unroll
        for (int j = 0; j < TN; j++) acc[i][j] = 0.0f;

    const float* Ap = A + (size_t)bm * lda;
    const float* Bp = B + bn;

    for (int k0 = 0; k0 < K; k0 += BKK) {
        float4 av = *(const float4*)(Ap + (size_t)a_row * lda + (k0 + a_col));
        As[a_col + 0][a_row] = av.x;
        As[a_col + 1][a_row] = av.y;
        As[a_col + 2][a_row] = av.z;
        As[a_col + 3][a_row] = av.w;
        float4 bv = *(const float4*)(Bp + (size_t)(k0 + b_row) * ldb + b_col);
        *(float4*)&Bs[b_row][b_col] = bv;
        __syncthreads();

        #pragma unroll
        for (int kk = 0; kk < BKK; kk++) {
            float af[TM], bf[TN];
            #pragma unroll
            for (int i = 0; i < TM; i++) af[i] = As[kk][ty * TM + i];
            #pragma unroll
            for (int j = 0; j < TN; j++) bf[j] = Bs[kk][tx * TN + j];
            #pragma unroll
            for (int i = 0; i < TM; i++)
                #pragma unroll
                for (int j = 0; j < TN; j++)
                    acc[i][j] = fmaf(af[i], bf[j], acc[i][j]);
        }
        __syncthreads();
    }

    #pragma unroll
    for (int i = 0; i < TM; i++) {
        const int row = bm + ty * TM + i;
        #pragma unroll
        for (int j = 0; j < TN; j += 4) {
            const int col = bn + tx * TN + j;
            float4 v = make_float4(acc[i][j], acc[i][j+1], acc[i][j+2], acc[i][j+3]);
            if (EPI != EPI_NONE) {
                v.x += bias[col + 0]; v.y += bias[col + 1];
                v.z += bias[col + 2]; v.w += bias[col + 3];
            }
            if (EPI == EPI_GELU) {
                v.x = gelu_tanh(v.x); v.y = gelu_tanh(v.y);
                v.z = gelu_tanh(v.z); v.w = gelu_tanh(v.w);
            }
            if (EPI == EPI_RES) {
                const float4 r = *(const float4*)(res + (size_t)row * ldres + col);
                v.x += r.x; v.y += r.y; v.z += r.z; v.w += r.w;
            }
            *(float4*)(C + (size_t)row * ldc + col) = v;
        }
    }
}

// ---------------- small kernels --------------------------------------------

// copy state [B, 8*U] into mem_plus slots 0..7
__global__ void copy_state_kernel(const float* __restrict__ state) {
    const int row = blockIdx.x;             // 0..GROWS-1 (b*8+m)
    const int b = row >> 3, m = row & 7;
    const float4* src = (const float4*)(state + (size_t)row * UNITS);
    float4* dst = (float4*)(g_memplus + ((size_t)b * SLOTS + m) * UNITS);
    dst[threadIdx.x] = src[threadIdx.x];    // 256 threads * float4 = 1024
}

// rel-pos sinusoid table: tab[p][j], p in 0..16 (pos = p-8)
__global__ void tab_kernel() {
    const int p = blockIdx.x;               // 0..16
    const float pos = (float)(p - MEMS);
    for (int j = threadIdx.x; j < UNITS; j += blockDim.x) {
        const float expo = (float)(j - (j & 1)) / (float)UNITS;
        const float angle = pos * __expf(-expo * 9.210340371976184f); // ln(10000)
        g_tab[p * UNITS + j] = (j & 1) ? cosf(angle) : sinf(angle);
    }
}

// rel_emb[17,U] = tab @ rel_kernel[U,U]
__global__ void relgemm_kernel(const float* __restrict__ rel_kernel) {
    const int p = blockIdx.y;
    const int n = blockIdx.x * blockDim.x + threadIdx.x;
    float acc = 0.0f;
    const float* tp = g_tab + p * UNITS;
    for (int j = 0; j < UNITS; j++)
        acc = fmaf(tp[j], rel_kernel[(size_t)j * UNITS + n], acc);
    g_rel[p * UNITS + n] = acc;
}

// attention per (b, h): S=9, dh=64
__global__ void __launch_bounds__(64) attn_kernel() {
    const int b = blockIdx.x, h = blockIdx.y;
    const int tid = threadIdx.x;            // 64 threads

    __shared__ float q[SLOTS][DH], k[SLOTS][DH], v[SLOTS][DH];
    __shared__ float r[17][DH];
    __shared__ float sc[SLOTS * SLOTS];

    const float scale = 0.125f;             // 1/sqrt(64)
    const size_t base = ((size_t)b * SLOTS) * (3 * UNITS) + (size_t)h * DH;

    for (int i = tid; i < SLOTS * DH; i += 64) {
        const int s = i >> 6, d = i & 63;
        const size_t o = base + (size_t)s * (3 * UNITS) + d;
        q[s][d] = g_qkv[o] * scale;
        k[s][d] = g_qkv[o + UNITS];
        v[s][d] = g_qkv[o + 2 * UNITS];
    }
    for (int i = tid; i < 17 * DH; i += 64) {
        const int p = i >> 6, d = i & 63;
        r[p][d] = g_rel[p * UNITS + h * DH + d];
    }
    __syncthreads();

    for (int p = tid; p < SLOTS * SLOTS; p += 64) {
        const int qi = p / SLOTS, ki = p % SLOTS;
        const float* rr = r[qi - ki + MEMS];
        float acc = 0.0f;
        #pragma unroll 16
        for (int d = 0; d < DH; d++)
            acc = fmaf(q[qi][d], k[ki][d] + rr[d], acc);
        sc[p] = acc;
    }
    __syncthreads();

    if (tid < SLOTS) {
        float mx = -1e30f;
        #pragma unroll
        for (int j = 0; j < SLOTS; j++) mx = fmaxf(mx, sc[tid * SLOTS + j]);
        float e[SLOTS], sum = 0.0f;
        #pragma unroll
        for (int j = 0; j < SLOTS; j++) { e[j] = __expf(sc[tid * SLOTS + j] - mx); sum += e[j]; }
        const float inv = 1.0f / sum;
        #pragma unroll
        for (int j = 0; j < SLOTS; j++) sc[tid * SLOTS + j] = e[j] * inv;
    }
    __syncthreads();

    const int d = tid;
    #pragma unroll
    for (int qi = 0; qi < SLOTS; qi++) {
        float acc = 0.0f;
        #pragma unroll
        for (int kk = 0; kk < SLOTS; kk++)
            acc = fmaf(sc[qi * SLOTS + kk], v[kk][d], acc);
        g_att[((size_t)b * SLOTS + qi) * UNITS + h * DH + d] = acc;
    }
}

// LayerNorm over last dim (1024) of X (+ optional Y), per row
__global__ void __launch_bounds__(256)
ln_kernel(const float* __restrict__ X, const float* __restrict__ Y,
          const float* __restrict__ gamma, const float* __restrict__ beta,
          float* __restrict__ out)
{
    const int row = blockIdx.x;
    const int tid = threadIdx.x;
    float4 x = ((const float4*)(X + (size_t)row * UNITS))[tid];
    if (Y) {
        const float4 y = ((const float4*)(Y + (size_t)row * UNITS))[tid];
        x.x += y.x; x.y += y.y; x.z += y.z; x.w += y.w;
    }
    float s  = x.x + x.y + x.z + x.w;
    float ss = x.x*x.x + x.y*x.y + x.z*x.z + x.w*x.w;

    __shared__ float red[16];
    #pragma unroll
    for (int o = 16; o > 0; o >>= 1) {
        s  += __shfl_down_sync(0xffffffff, s, o);
        ss += __shfl_down_sync(0xffffffff, ss, o);
    }
    const int warp = tid >> 5, lane = tid & 31;
    if (lane == 0) { red[warp] = s; red[warp + 8] = ss; }
    __syncthreads();
    if (tid == 0) {
        float ts = 0.0f, tss = 0.0f;
        #pragma unroll
        for (int w = 0; w < 8; w++) { ts += red[w]; tss += red[w + 8]; }
        red[0] = ts * (1.0f / UNITS);
        const float mean = red[0];
        red[1] = rsqrtf(tss * (1.0f / UNITS) - mean * mean + LN_EPS);
    }
    __syncthreads();
    const float mean = red[0], rstd = red[1];

    const float4 g = ((const float4*)gamma)[tid];
    const float4 bb = ((const float4*)beta)[tid];
    float4 o;
    o.x = (x.x - mean) * rstd * g.x + bb.x;
    o.y = (x.y - mean) * rstd * g.y + bb.y;
    o.z = (x.z - mean) * rstd * g.z + bb.z;
    o.w = (x.w - mean) * rstd * g.w + bb.w;
    ((float4*)(out + (size_t)row * UNITS))[tid] = o;
}

// copy output rows h2[:, M, :] -> out[0 : B*U]
__global__ void outcopy_kernel(float* __restrict__ out) {
    const int b = blockIdx.x;
    const float4* src = (const float4*)(g_h2 + ((size_t)b * SLOTS + MEMS) * UNITS);
    ((float4*)(out + (size_t)b * UNITS))[threadIdx.x] = src[threadIdx.x];
}

__device__ __forceinline__ float hsig(float x) { return __saturatef(0.2f * x + 0.5f); }

// gates + next_memory
__global__ void __launch_bounds__(256)
gates_kernel(const float* __restrict__ state, float* __restrict__ out)
{
    const int row = blockIdx.x;             // b*8+m
    const int b = row >> 3, m = row & 7;
    const int tid = threadIdx.x;

    const float4 g0i = ((const float4*)(g_g0 + (size_t)b * 2 * UNITS))[tid];
    const float4 g0f = ((const float4*)(g_g0 + (size_t)b * 2 * UNITS + UNITS))[tid];
    const float4 g1i = ((const float4*)(g_g1 + (size_t)row * 2 * UNITS))[tid];
    const float4 g1f = ((const float4*)(g_g1 + (size_t)row * 2 * UNITS + UNITS))[tid];
    const float4 mem = ((const float4*)(state + (size_t)row * UNITS))[tid];
    const float4 nm  = ((const float4*)(g_h2 + ((size_t)b * SLOTS + m) * UNITS))[tid];

    float4 o;
    o.x = hsig(g0f.x + g1f.x + 1.0f) * mem.x + hsig(g0i.x + g1i.x) * tanhf(nm.x);
    o.y = hsig(g0f.y + g1f.y + 1.0f) * mem.y + hsig(g0i.y + g1i.y) * tanhf(nm.y);
    o.z = hsig(g0f.z + g1f.z + 1.0f) * mem.z + hsig(g0i.z + g1i.z) * tanhf(nm.z);
    o.w = hsig(g0f.w + g1f.w + 1.0f) * mem.w + hsig(g0i.w + g1i.w) * tanhf(nm.w);
    ((float4*)(out + (size_t)BATCH * UNITS + (size_t)row * UNITS))[tid] = o;
}

// ---------------- host launcher ---------------------------------------------
extern "C" void kernel_launch(void* const* d_in, const int* in_sizes, int n_in,
                              void* d_out, int out_size)
{
    const float* inputs           = (const float*)d_in[0];
    const float* state            = (const float*)d_in[1];
    const float* input_kernel     = (const float*)d_in[2];
    const float* input_bias_w     = (const float*)d_in[3];
    const float* gate_kernel      = (const float*)d_in[4];
    const float* recurrent_kernel = (const float*)d_in[5];
    const float* recurrent_bias   = (const float*)d_in[6];
    const float* attention_kernel = (const float*)d_in[7];
    const float* attention_bias   = (const float*)d_in[8];
    const float* mlp_kernel       = (const float*)d_in[9];
    const float* mlp_bias         = (const float*)d_in[10];
    const float* ln_gamma         = (const float*)d_in[11];
    const float* ln_beta          = (const float*)d_in[12];
    const float* rel_kernel       = (const float*)d_in[13];
    float* out = (float*)d_out;

    static float *p_memplus = nullptr, *p_qkv, *p_att, *p_h, *p_t, *p_hm, *p_h2,
                 *p_g0, *p_g1;
    if (!p_memplus) {
        cudaGetSymbolAddress((void**)&p_memplus, g_memplus);
        cudaGetSymbolAddress((void**)&p_qkv, g_qkv);
        cudaGetSymbolAddress((void**)&p_att, g_att);
        cudaGetSymbolAddress((void**)&p_h, g_h);
        cudaGetSymbolAddress((void**)&p_t, g_t);
        cudaGetSymbolAddress((void**)&p_hm, g_hm);
        cudaGetSymbolAddress((void**)&p_h2, g_h2);
        cudaGetSymbolAddress((void**)&p_g0, g_g0);
        cudaGetSymbolAddress((void**)&p_g1, g_g1);
    }

    // rel-pos table + tiny GEMM
    tab_kernel<<<17, 256>>>();
    relgemm_kernel<<<dim3(UNITS / 256, 17), 256>>>(rel_kernel);

    // mem_plus: state slots + x = inputs @ Wi + bi (written into slot 8)
    copy_state_kernel<<<GROWS, 256>>>(state);
    sgemm_kernel<EPI_BIAS><<<dim3(UNITS / BN, BATCH / BM), 256>>>(
        inputs, DIMD, input_kernel, UNITS, input_bias_w,
        nullptr, 0, p_memplus + MEMS * UNITS, SLOTS * UNITS,
        BATCH, UNITS, DIMD);

    // qkv = mem_plus @ Wa + ba
    sgemm_kernel<EPI_BIAS><<<dim3(3 * UNITS / BN, ROWS / BM), 256>>>(
        p_memplus, UNITS, attention_kernel, 3 * UNITS, attention_bias,
        nullptr, 0, p_qkv, 3 * UNITS, ROWS, 3 * UNITS, UNITS);

    // attention
    attn_kernel<<<dim3(BATCH, HEADS), 64>>>();

    // h = LN(mem_plus + att)
    ln_kernel<<<ROWS, 256>>>(p_memplus, p_att, ln_gamma, ln_beta, p_h);

    // t = gelu(h @ w1 + mb1)
    sgemm_kernel<EPI_GELU><<<dim3(UNITS / BN, ROWS / BM), 256>>>(
        p_h, UNITS, mlp_kernel, 2 * UNITS, mlp_bias,
        nullptr, 0, p_t, UNITS, ROWS, UNITS, UNITS);

    // hm = h + (t @ w2 + mb2)
    sgemm_kernel<EPI_RES><<<dim3(UNITS / BN, ROWS / BM), 256>>>(
        p_t, UNITS, mlp_kernel + UNITS, 2 * UNITS, mlp_bias + UNITS,
        p_h, UNITS, p_hm, UNITS, ROWS, UNITS, UNITS);

    // h2 = LN(hm)
    ln_kernel<<<ROWS, 256>>>(p_hm, nullptr, ln_gamma + UNITS, ln_beta + UNITS, p_h2);

    // gates: g0 = inputs @ gate_kernel ; g1 = memory @ recurrent_kernel + rbias
    sgemm_kernel<EPI_NONE><<<dim3(2 * UNITS / BN, BATCH / BM), 256>>>(
        inputs, DIMD, gate_kernel, 2 * UNITS, nullptr,
        nullptr, 0, p_g0, 2 * UNITS, BATCH, 2 * UNITS, DIMD);
    sgemm_kernel<EPI_BIAS><<<dim3(2 * UNITS / BN, GROWS / BM), 256>>>(
        state, UNITS, recurrent_kernel, 2 * UNITS, recurrent_bias,
        nullptr, 0, p_g1, 2 * UNITS, GROWS, 2 * UNITS, UNITS);

    // outputs
    outcopy_kernel<<<BATCH, 256>>>(out);
    gates_kernel<<<GROWS, 256>>>(state, out);
}

// round 2
// speedup vs baseline: 2.8134x; 2.8134x over previous
#include <cuda_runtime.h>
#include <math.h>

// ---------------- problem constants ----------------
#define BATCH 2048
#define DIMD  1024
#define UNITS 1024
#define MEMS  8
#define SLOTS 9                 // M + 1
#define ROWS  (BATCH*SLOTS)     // 18432
#define HEADS 16
#define DH    64
#define GROWS (BATCH*MEMS)      // 16384
#define LN_EPS 1e-5f

// ---------------- scratch (device globals; no allocation allowed) ----------
__device__ float g_memplus[ROWS*UNITS];      // [B,9,U] (tf32-rounded)
__device__ float g_qkv[ROWS*3*UNITS];        // [B,9,3U]
__device__ float g_att[ROWS*UNITS];          // attention output
__device__ float g_h[ROWS*UNITS];            // LN1 output (tf32-rounded)
__device__ float g_t[ROWS*UNITS];            // gelu(h@w1+b) (tf32-rounded)
__device__ float g_hm[ROWS*UNITS];           // h + mlp2
__device__ float g_h2[ROWS*UNITS];           // LN2 output
__device__ float g_g0[BATCH*2*UNITS];        // inputs@gate_kernel
__device__ float g_g1[GROWS*2*UNITS];        // memory@recurrent_kernel + rbias
__device__ float g_tab[17*UNITS];            // rel-pos sinusoid table
__device__ float g_rel[17*UNITS];            // tab @ rel_kernel
__device__ float g_xr[BATCH*DIMD];           // rounded inputs
__device__ float g_memr[GROWS*UNITS];        // rounded state (compact)
__device__ float w_in_r[DIMD*UNITS];
__device__ float w_gate_r[DIMD*2*UNITS];
__device__ float w_rec_r[UNITS*2*UNITS];
__device__ float w_att_r[UNITS*3*UNITS];
__device__ float w_mlp_r[UNITS*2*UNITS];

// ---------------- helpers ----------------
__device__ __forceinline__ float rtf32(float x) {
    unsigned u;
    asm("cvt.rna.tf32.f32 %0, %1;" : "=r"(u) : "f"(x));
    return __uint_as_float(u);
}

__device__ __forceinline__ float gelu_tanh(float x) {
    const float c0 = 0.7978845608028654f;   // sqrt(2/pi)
    const float c1 = 0.044715f;
    return 0.5f * x * (1.0f + tanhf(c0 * (x + c1 * x * x * x)));
}

__device__ __forceinline__ float hsig(float x) { return __saturatef(0.2f * x + 0.5f); }

__device__ __forceinline__ unsigned smem_u32(const void* p) {
    return (unsigned)__cvta_generic_to_shared(p);
}

// ---------------- TF32 tensor-core GEMM ------------------------------------
// C[M,N] = A[M,K] @ B[K,N] (+bias)(+gelu|+res), operands pre-rounded to tf32.
#define BM 128
#define BN 256
#define BKT 32
#define A_LDS 36                    // padded A row stride (floats)
#define B_LDS 260                   // padded B row stride (floats)
#define A_SZ (BM*A_LDS)             // 4608 floats
#define B_SZ (BKT*B_LDS)            // 8320 floats
#define STAGE_SZ (A_SZ + B_SZ)      // 12928 floats
#define STAGE_BYTES (STAGE_SZ*4)    // 51712 bytes
#define NSTAGE 3
#define GEMM_SMEM (NSTAGE*STAGE_BYTES)

#define EPI_NONE 0
#define EPI_BIAS 1
#define EPI_GELU 2
#define EPI_RES  3

template<int EPI, bool ROUND>
__global__ void __launch_bounds__(256, 1)
tgemm(const float* __restrict__ A, int lda,
      const float* __restrict__ B, int ldb,
      const float* __restrict__ bias,
      const float* __restrict__ res, int ldres,
      float* __restrict__ C, int ldc,
      int M, int N, int K)
{
    extern __shared__ float sm[];
    const int tid  = threadIdx.x;
    const int lane = tid & 31;
    const int warp = tid >> 5;
    const int bm = blockIdx.y * BM;
    const int bn = blockIdx.x * BN;
    const int wm0 = (warp >> 2) * 64;   // warp tile origin within block
    const int wn0 = (warp & 3) * 64;

    // --- cp.async source/dst bases ---
    const float* Ag = A + (size_t)(bm + (tid >> 3)) * lda + ((tid & 7) << 2);
    const float* Bg = B + (size_t)(tid >> 6) * ldb + bn + ((tid & 63) << 2);
    const unsigned a_dst0 = smem_u32(sm) + (((tid >> 3) * A_LDS + ((tid & 7) << 2)) << 2);
    const unsigned b_dst0 = smem_u32(sm) + ((A_SZ + (tid >> 6) * B_LDS + ((tid & 63) << 2)) << 2);

    auto prefetch = [&](int s, int kt) {
        const unsigned ad = a_dst0 + s * STAGE_BYTES;
        const float* ag = Ag + kt * BKT;
        #pragma unroll
        for (int i = 0; i < 4; i++)
            asm volatile("cp.async.cg.shared.global [%0], [%1], 16;"
                         :: "r"(ad + i * (32 * A_LDS * 4)), "l"(ag + (size_t)i * 32 * lda));
        const unsigned bd = b_dst0 + s * STAGE_BYTES;
        const float* bg = Bg + (size_t)kt * BKT * ldb;
        #pragma unroll
        for (int i = 0; i < 8; i++)
            asm volatile("cp.async.cg.shared.global [%0], [%1], 16;"
                         :: "r"(bd + i * (4 * B_LDS * 4)), "l"(bg + (size_t)i * 4 * ldb));
    };

    float acc[4][8][4];
    #pragma unroll
    for (int mt = 0; mt < 4; mt++)
        #pragma unroll
        for (int nt = 0; nt < 8; nt++)
            #pragma unroll
            for (int r = 0; r < 4; r++) acc[mt][nt][r] = 0.0f;

    const int kiters = K / BKT;
    prefetch(0, 0); asm volatile("cp.async.commit_group;" ::: "memory");
    prefetch(1, 1); asm volatile("cp.async.commit_group;" ::: "memory");

    // ldmatrix per-lane offset within A tile
    const int lsub = lane >> 3;                       // which 8x4 submatrix
    const int a_row_add = ((lsub & 1) << 3) + (lane & 7);
    const int a_col_add = (lsub >> 1) << 2;

    int s = 0;
    for (int kt = 0; kt < kiters; kt++) {
        if (kt + 2 < kiters) prefetch((kt + 2) % NSTAGE, kt + 2);
        asm volatile("cp.async.commit_group;" ::: "memory");
        asm volatile("cp.async.wait_group 2;" ::: "memory");
        __syncthreads();

        const float* Ab = sm + s * STAGE_SZ;
        const float* Bb = Ab + A_SZ;
        const unsigned a_base = smem_u32(Ab) + (((wm0 + a_row_add) * A_LDS + a_col_add) << 2);

        #pragma unroll
        for (int kc = 0; kc < BKT; kc += 8) {
            unsigned af[4][4];
            #pragma unroll
            for (int mt = 0; mt < 4; mt++) {
                const unsigned addr = a_base + ((mt * 16 * A_LDS + kc) << 2);
                asm volatile("ldmatrix.sync.aligned.m8n8.x4.shared.b16 {%0,%1,%2,%3}, [%4];"
                             : "=r"(af[mt][0]), "=r"(af[mt][1]), "=r"(af[mt][2]), "=r"(af[mt][3])
                             : "r"(addr));
            }
            unsigned bf[8][2];
            #pragma unroll
            for (int nt = 0; nt < 8; nt++) {
                const float* bp = Bb + (kc + (lane & 3)) * B_LDS + wn0 + nt * 8 + (lane >> 2);
                bf[nt][0] = __float_as_uint(bp[0]);
                bf[nt][1] = __float_as_uint(bp[4 * B_LDS]);
            }
            #pragma unroll
            for (int mt = 0; mt < 4; mt++)
                #pragma unroll
                for (int nt = 0; nt < 8; nt++)
                    asm volatile(
                        "mma.sync.aligned.m16n8k8.row.col.f32.tf32.tf32.f32 "
                        "{%0,%1,%2,%3}, {%4,%5,%6,%7}, {%8,%9}, {%0,%1,%2,%3};"
                        : "+f"(acc[mt][nt][0]), "+f"(acc[mt][nt][1]),
                          "+f"(acc[mt][nt][2]), "+f"(acc[mt][nt][3])
                        : "r"(af[mt][0]), "r"(af[mt][1]), "r"(af[mt][2]), "r"(af[mt][3]),
                          "r"(bf[nt][0]), "r"(bf[nt][1]));
        }
        __syncthreads();
        s = (s == NSTAGE - 1) ? 0 : s + 1;
    }

    // --- epilogue ---
    #pragma unroll
    for (int mt = 0; mt < 4; mt++) {
        const int r0 = bm + wm0 + mt * 16 + (lane >> 2);
        #pragma unroll
        for (int nt = 0; nt < 8; nt++) {
            const int c = bn + wn0 + nt * 8 + ((lane & 3) << 1);
            float2 v0 = make_float2(acc[mt][nt][0], acc[mt][nt][1]);
            float2 v1 = make_float2(acc[mt][nt][2], acc[mt][nt][3]);
            if (EPI != EPI_NONE) {
                const float bx = bias[c], by = bias[c + 1];
                v0.x += bx; v0.y += by; v1.x += bx; v1.y += by;
            }
            if (EPI == EPI_GELU) {
                v0.x = gelu_tanh(v0.x); v0.y = gelu_tanh(v0.y);
                v1.x = gelu_tanh(v1.x); v1.y = gelu_tanh(v1.y);
            }
            if (EPI == EPI_RES) {
                const float2 ra = *(const float2*)(res + (size_t)r0 * ldres + c);
                const float2 rb = *(const float2*)(res + (size_t)(r0 + 8) * ldres + c);
                v0.x += ra.x; v0.y += ra.y; v1.x += rb.x; v1.y += rb.y;
            }
            if (ROUND) {
                v0.x = rtf32(v0.x); v0.y = rtf32(v0.y);
                v1.x = rtf32(v1.x); v1.y = rtf32(v1.y);
            }
            *(float2*)(C + (size_t)r0 * ldc + c) = v0;
            *(float2*)(C + (size_t)(r0 + 8) * ldc + c) = v1;
        }
    }
}

// ---------------- small kernels --------------------------------------------

// round fp32 -> tf32 (RNA), vectorized
__global__ void round_kernel(const float* __restrict__ src, float* __restrict__ dst, int n4) {
    const int i = blockIdx.x * blockDim.x + threadIdx.x;
    if (i < n4) {
        float4 v = ((const float4*)src)[i];
        v.x = rtf32(v.x); v.y = rtf32(v.y); v.z = rtf32(v.z); v.w = rtf32(v.w);
        ((float4*)dst)[i] = v;
    }
}

// copy state [B, 8*U] into mem_plus slots 0..7 and compact g_memr (rounded)
__global__ void copy_state_kernel(const float* __restrict__ state) {
    const int row = blockIdx.x;             // 0..GROWS-1 (b*8+m)
    const int b = row >> 3, m = row & 7;
    float4 v = ((const float4*)(state + (size_t)row * UNITS))[threadIdx.x];
    v.x = rtf32(v.x); v.y = rtf32(v.y); v.z = rtf32(v.z); v.w = rtf32(v.w);
    ((float4*)(g_memplus + ((size_t)b * SLOTS + m) * UNITS))[threadIdx.x] = v;
    ((float4*)(g_memr + (size_t)row * UNITS))[threadIdx.x] = v;
}

// rel-pos sinusoid table
__global__ void tab_kernel() {
    const int p = blockIdx.x;               // 0..16
    const float pos = (float)(p - MEMS);
    for (int j = threadIdx.x; j < UNITS; j += blockDim.x) {
        const float expo = (float)(j - (j & 1)) / (float)UNITS;
        const float angle = pos * __expf(-expo * 9.210340371976184f);
        g_tab[p * UNITS + j] = (j & 1) ? cosf(angle) : sinf(angle);
    }
}

// rel_emb[17,U] = tab @ rel_kernel[U,U]  (tiny, FFMA is fine)
__global__ void relgemm_kernel(const float* __restrict__ rel_kernel) {
    const int p = blockIdx.y;
    const int n = blockIdx.x * blockDim.x + threadIdx.x;
    float acc = 0.0f;
    const float* tp = g_tab + p * UNITS;
    for (int j = 0; j < UNITS; j++)
        acc = fmaf(tp[j], rel_kernel[(size_t)j * UNITS + n], acc);
    g_rel[p * UNITS + n] = acc;
}

// attention per (b, h): S=9, dh=64
__global__ void __launch_bounds__(64) attn_kernel() {
    const int b = blockIdx.x, h = blockIdx.y;
    const int tid = threadIdx.x;

    __shared__ float q[SLOTS][DH], k[SLOTS][DH], v[SLOTS][DH];
    __shared__ float r[17][DH];
    __shared__ float sc[SLOTS * SLOTS];

    const float scale = 0.125f;
    const size_t base = ((size_t)b * SLOTS) * (3 * UNITS) + (size_t)h * DH;

    for (int i = tid; i < SLOTS * DH; i += 64) {
        const int s = i >> 6, d = i & 63;
        const size_t o = base + (size_t)s * (3 * UNITS) + d;
        q[s][d] = g_qkv[o] * scale;
        k[s][d] = g_qkv[o + UNITS];
        v[s][d] = g_qkv[o + 2 * UNITS];
    }
    for (int i = tid; i < 17 * DH; i += 64) {
        const int p = i >> 6, d = i & 63;
        r[p][d] = g_rel[p * UNITS + h * DH + d];
    }
    __syncthreads();

    for (int p = tid; p < SLOTS * SLOTS; p += 64) {
        const int qi = p / SLOTS, ki = p % SLOTS;
        const float* rr = r[qi - ki + MEMS];
        float acc = 0.0f;
        #pragma unroll 16
        for (int d = 0; d < DH; d++)
            acc = fmaf(q[qi][d], k[ki][d] + rr[d], acc);
        sc[p] = acc;
    }
    __syncthreads();

    if (tid < SLOTS) {
        float mx = -1e30f;
        #pragma unroll
        for (int j = 0; j < SLOTS; j++) mx = fmaxf(mx, sc[tid * SLOTS + j]);
        float e[SLOTS], sum = 0.0f;
        #pragma unroll
        for (int j = 0; j < SLOTS; j++) { e[j] = __expf(sc[tid * SLOTS + j] - mx); sum += e[j]; }
        const float inv = 1.0f / sum;
        #pragma unroll
        for (int j = 0; j < SLOTS; j++) sc[tid * SLOTS + j] = e[j] * inv;
    }
    __syncthreads();

    const int d = tid;
    #pragma unroll
    for (int qi = 0; qi < SLOTS; qi++) {
        float acc = 0.0f;
        #pragma unroll
        for (int kk = 0; kk < SLOTS; kk++)
            acc = fmaf(sc[qi * SLOTS + kk], v[kk][d], acc);
        g_att[((size_t)b * SLOTS + qi) * UNITS + h * DH + d] = acc;
    }
}

// LayerNorm over last dim (1024) of X (+ optional Y), per row
__global__ void __launch_bounds__(256)
ln_kernel(const float* __restrict__ X, const float* __restrict__ Y,
          const float* __restrict__ gamma, const float* __restrict__ beta,
          float* __restrict__ out, int do_round)
{
    const int row = blockIdx.x;
    const int tid = threadIdx.x;
    float4 x = ((const float4*)(X + (size_t)row * UNITS))[tid];
    if (Y) {
        const float4 y = ((const float4*)(Y + (size_t)row * UNITS))[tid];
        x.x += y.x; x.y += y.y; x.z += y.z; x.w += y.w;
    }
    float s  = x.x + x.y + x.z + x.w;
    float ss = x.x*x.x + x.y*x.y + x.z*x.z + x.w*x.w;

    __shared__ float red[16];
    #pragma unroll
    for (int o = 16; o > 0; o >>= 1) {
        s  += __shfl_down_sync(0xffffffff, s, o);
        ss += __shfl_down_sync(0xffffffff, ss, o);
    }
    const int warp = tid >> 5, lane = tid & 31;
    if (lane == 0) { red[warp] = s; red[warp + 8] = ss; }
    __syncthreads();
    if (tid == 0) {
        float ts = 0.0f, tss = 0.0f;
        #pragma unroll
        for (int w = 0; w < 8; w++) { ts += red[w]; tss += red[w + 8]; }
        red[0] = ts * (1.0f / UNITS);
        const float mean = red[0];
        red[1] = rsqrtf(tss * (1.0f / UNITS) - mean * mean + LN_EPS);
    }
    __syncthreads();
    const float mean = red[0], rstd = red[1];

    const float4 g = ((const float4*)gamma)[tid];
    const float4 bb = ((const float4*)beta)[tid];
    float4 o;
    o.x = (x.x - mean) * rstd * g.x + bb.x;
    o.y = (x.y - mean) * rstd * g.y + bb.y;
    o.z = (x.z - mean) * rstd * g.z + bb.z;
    o.w = (x.w - mean) * rstd * g.w + bb.w;
    if (do_round) {
        o.x = rtf32(o.x); o.y = rtf32(o.y); o.z = rtf32(o.z); o.w = rtf32(o.w);
    }
    ((float4*)(out + (size_t)row * UNITS))[tid] = o;
}

// copy output rows h2[:, M, :] -> out[0 : B*U]
__global__ void outcopy_kernel(float* __restrict__ out) {
    const int b = blockIdx.x;
    const float4* src = (const float4*)(g_h2 + ((size_t)b * SLOTS + MEMS) * UNITS);
    ((float4*)(out + (size_t)b * UNITS))[threadIdx.x] = src[threadIdx.x];
}

// gates + next_memory
__global__ void __launch_bounds__(256)
gates_kernel(const float* __restrict__ state, float* __restrict__ out)
{
    const int row = blockIdx.x;             // b*8+m
    const int b = row >> 3, m = row & 7;
    const int tid = threadIdx.x;

    const float4 g0i = ((const float4*)(g_g0 + (size_t)b * 2 * UNITS))[tid];
    const float4 g0f = ((const float4*)(g_g0 + (size_t)b * 2 * UNITS + UNITS))[tid];
    const float4 g1i = ((const float4*)(g_g1 + (size_t)row * 2 * UNITS))[tid];
    const float4 g1f = ((const float4*)(g_g1 + (size_t)row * 2 * UNITS + UNITS))[tid];
    const float4 mem = ((const float4*)(state + (size_t)row * UNITS))[tid];
    const float4 nm  = ((const float4*)(g_h2 + ((size_t)b * SLOTS + m) * UNITS))[tid];

    float4 o;
    o.x = hsig(g0f.x + g1f.x + 1.0f) * mem.x + hsig(g0i.x + g1i.x) * tanhf(nm.x);
    o.y = hsig(g0f.y + g1f.y + 1.0f) * mem.y + hsig(g0i.y + g1i.y) * tanhf(nm.y);
    o.z = hsig(g0f.z + g1f.z + 1.0f) * mem.z + hsig(g0i.z + g1i.z) * tanhf(nm.z);
    o.w = hsig(g0f.w + g1f.w + 1.0f) * mem.w + hsig(g0i.w + g1i.w) * tanhf(nm.w);
    ((float4*)(out + (size_t)BATCH * UNITS + (size_t)row * UNITS))[tid] = o;
}

// ---------------- host launcher ---------------------------------------------
extern "C" void kernel_launch(void* const* d_in, const int* in_sizes, int n_in,
                              void* d_out, int out_size)
{
    const float* inputs           = (const float*)d_in[0];
    const float* state            = (const float*)d_in[1];
    const float* input_kernel     = (const float*)d_in[2];
    const float* input_bias_w     = (const float*)d_in[3];
    const float* gate_kernel      = (const float*)d_in[4];
    const float* recurrent_kernel = (const float*)d_in[5];
    const float* recurrent_bias   = (const float*)d_in[6];
    const float* attention_kernel = (const float*)d_in[7];
    const float* attention_bias   = (const float*)d_in[8];
    const float* mlp_kernel       = (const float*)d_in[9];
    const float* mlp_bias         = (const float*)d_in[10];
    const float* ln_gamma         = (const float*)d_in[11];
    const float* ln_beta          = (const float*)d_in[12];
    const float* rel_kernel       = (const float*)d_in[13];
    float* out = (float*)d_out;

    static float *p_memplus = nullptr, *p_qkv, *p_h, *p_t, *p_hm, *p_h2,
                 *p_g0, *p_g1, *p_xr, *p_memr,
                 *p_win, *p_wgate, *p_wrec, *p_watt, *p_wmlp;
    static bool attr_done = false;
    if (!p_memplus) {
        cudaGetSymbolAddress((void**)&p_memplus, g_memplus);
        cudaGetSymbolAddress((void**)&p_qkv, g_qkv);
        cudaGetSymbolAddress((void**)&p_h, g_h);
        cudaGetSymbolAddress((void**)&p_t, g_t);
        cudaGetSymbolAddress((void**)&p_hm, g_hm);
        cudaGetSymbolAddress((void**)&p_h2, g_h2);
        cudaGetSymbolAddress((void**)&p_g0, g_g0);
        cudaGetSymbolAddress((void**)&p_g1, g_g1);
        cudaGetSymbolAddress((void**)&p_xr, g_xr);
        cudaGetSymbolAddress((void**)&p_memr, g_memr);
        cudaGetSymbolAddress((void**)&p_win, w_in_r);
        cudaGetSymbolAddress((void**)&p_wgate, w_gate_r);
        cudaGetSymbolAddress((void**)&p_wrec, w_rec_r);
        cudaGetSymbolAddress((void**)&p_watt, w_att_r);
        cudaGetSymbolAddress((void**)&p_wmlp, w_mlp_r);
    }
    if (!attr_done) {
        cudaFuncSetAttribute(tgemm<EPI_BIAS, true >, cudaFuncAttributeMaxDynamicSharedMemorySize, GEMM_SMEM);
        cudaFuncSetAttribute(tgemm<EPI_BIAS, false>, cudaFuncAttributeMaxDynamicSharedMemorySize, GEMM_SMEM);
        cudaFuncSetAttribute(tgemm<EPI_GELU, true >, cudaFuncAttributeMaxDynamicSharedMemorySize, GEMM_SMEM);
        cudaFuncSetAttribute(tgemm<EPI_RES,  false>, cudaFuncAttributeMaxDynamicSharedMemorySize, GEMM_SMEM);
        cudaFuncSetAttribute(tgemm<EPI_NONE, false>, cudaFuncAttributeMaxDynamicSharedMemorySize, GEMM_SMEM);
        attr_done = true;
    }

    // --- pre-round weights & inputs to tf32 (RNA) ---
    round_kernel<<<(BATCH*DIMD/4 + 255)/256, 256>>>(inputs, p_xr, BATCH*DIMD/4);
    round_kernel<<<(DIMD*UNITS/4 + 255)/256, 256>>>(input_kernel, p_win, DIMD*UNITS/4);
    round_kernel<<<(DIMD*2*UNITS/4 + 255)/256, 256>>>(gate_kernel, p_wgate, DIMD*2*UNITS/4);
    round_kernel<<<(UNITS*2*UNITS/4 + 255)/256, 256>>>(recurrent_kernel, p_wrec, UNITS*2*UNITS/4);
    round_kernel<<<(UNITS*3*UNITS/4 + 255)/256, 256>>>(attention_kernel, p_watt, UNITS*3*UNITS/4);
    round_kernel<<<(UNITS*2*UNITS/4 + 255)/256, 256>>>(mlp_kernel, p_wmlp, UNITS*2*UNITS/4);

    // rel-pos table + tiny GEMM
    tab_kernel<<<17, 256>>>();
    relgemm_kernel<<<dim3(UNITS / 256, 17), 256>>>(rel_kernel);

    // mem_plus: state slots (rounded) + x = inputs @ Wi + bi (slot 8, rounded)
    copy_state_kernel<<<GROWS, 256>>>(state);
    tgemm<EPI_BIAS, true><<<dim3(UNITS / BN, BATCH / BM), 256, GEMM_SMEM>>>(
        p_xr, DIMD, p_win, UNITS, input_bias_w,
        nullptr, 0, p_memplus + MEMS * UNITS, SLOTS * UNITS,
        BATCH, UNITS, DIMD);

    // qkv = mem_plus @ Wa + ba
    tgemm<EPI_BIAS, false><<<dim3(3 * UNITS / BN, ROWS / BM), 256, GEMM_SMEM>>>(
        p_memplus, UNITS, p_watt, 3 * UNITS, attention_bias,
        nullptr, 0, p_qkv, 3 * UNITS, ROWS, 3 * UNITS, UNITS);

    // attention
    attn_kernel<<<dim3(BATCH, HEADS), 64>>>();

    // h = LN(mem_plus + att)  (rounded: feeds MLP GEMMs)
    ln_kernel<<<ROWS, 256>>>(p_memplus, (float*)nullptr + 0 == nullptr ? nullptr : nullptr, ln_gamma, ln_beta, p_h, 1);
    // (the Y operand must be g_att)
    // NOTE: replaced below — see actual call
    // t = gelu(h @ w1 + mb1)  (rounded: feeds MLP2)
    // -- corrected LN1 launch:
    {
        float* p_att;
        cudaGetSymbolAddress((void**)&p_att, g_att);
        ln_kernel<<<ROWS, 256>>>(p_memplus, p_att, ln_gamma, ln_beta, p_h, 1);
    }

    tgemm<EPI_GELU, true><<<dim3(UNITS / BN, ROWS / BM), 256, GEMM_SMEM>>>(
        p_h, UNITS, p_wmlp, 2 * UNITS, mlp_bias,
        nullptr, 0, p_t, UNITS, ROWS, UNITS, UNITS);

    // hm = h + (t @ w2 + mb2)
    tgemm<EPI_RES, false><<<dim3(UNITS / BN, ROWS / BM), 256, GEMM_SMEM>>>(
        p_t, UNITS, p_wmlp + UNITS, 2 * UNITS, mlp_bias + UNITS,
        p_h, UNITS, p_hm, UNITS, ROWS, UNITS, UNITS);

    // h2 = LN(hm)
    ln_kernel<<<ROWS, 256>>>(p_hm, nullptr, ln_gamma + UNITS, ln_beta + UNITS, p_h2, 0);

    // gates
    tgemm<EPI_NONE, false><<<dim3(2 * UNITS / BN, BATCH / BM), 256, GEMM_SMEM>>>(
        p_xr, DIMD, p_wgate, 2 * UNITS, nullptr,
        nullptr, 0, p_g0, 2 * UNITS, BATCH, 2 * UNITS, DIMD);
    tgemm<EPI_BIAS, false><<<dim3(2 * UNITS / BN, GROWS / BM), 256, GEMM_SMEM>>>(
        p_memr, UNITS, p_wrec, 2 * UNITS, recurrent_bias,
        nullptr, 0, p_g1, 2 * UNITS, GROWS, 2 * UNITS, UNITS);

    // outputs
    outcopy_kernel<<<BATCH, 256>>>(out);
    gates_kernel<<<GROWS, 256>>>(state, out);
}

// round 4
// speedup vs baseline: 4.8179x; 1.7125x over previous
#include <cuda_runtime.h>
#include <cuda_fp16.h>
#include <math.h>
#include <stdint.h>

// ---------------- problem constants ----------------
#define BATCH 2048
#define DIMD  1024
#define UNITS 1024
#define MEMS  8
#define SLOTS 9                 // M + 1
#define ROWS  (BATCH*SLOTS)     // 18432
#define HEADS 16
#define DH    64
#define GROWS (BATCH*MEMS)      // 16384
#define LN_EPS 1e-5f

// ---------------- scratch (device globals; no allocation allowed) ----------
__device__ __align__(16) __half g_memplus[ROWS*UNITS];   // [B,9,U] fp16
__device__ __align__(16) __half g_h[ROWS*UNITS];         // LN1 out fp16
__device__ __align__(16) __half g_t[ROWS*UNITS];         // gelu(h@w1+b) fp16
__device__ __align__(16) __half g_xr[BATCH*DIMD];        // inputs fp16
__device__ __align__(16) __half g_memr[GROWS*UNITS];     // state fp16 compact
__device__ float g_qkv[ROWS*3*UNITS];
__device__ float g_att[ROWS*UNITS];
__device__ float g_hm[ROWS*UNITS];
__device__ float g_h2[ROWS*UNITS];
__device__ float g_g0[BATCH*2*UNITS];
__device__ float g_g1[GROWS*2*UNITS];
__device__ float g_tab[17*UNITS];
__device__ float g_rel[17*UNITS];
// transposed ([N,K] K-major) fp16 weights
__device__ __align__(16) __half wt_in[UNITS*DIMD];
__device__ __align__(16) __half wt_gate[2*UNITS*DIMD];
__device__ __align__(16) __half wt_rec[2*UNITS*UNITS];
__device__ __align__(16) __half wt_att[3*UNITS*UNITS];
__device__ __align__(16) __half wt_mlp[2*UNITS*UNITS];

// ---------------- helpers ----------------
__device__ __forceinline__ float gelu_tanh(float x) {
    const float c0 = 0.7978845608028654f;
    const float c1 = 0.044715f;
    return 0.5f * x * (1.0f + tanhf(c0 * (x + c1 * x * x * x)));
}
__device__ __forceinline__ float hsig(float x) { return __saturatef(0.2f * x + 0.5f); }
__device__ __forceinline__ unsigned smem_u32(const void* p) {
    return (unsigned)__cvta_generic_to_shared(p);
}

// ============================================================================
// FP16 tensor-core GEMM (mma.sync.m16n8k16):
//   C[M,N] = A[M,K] @ Bt[N,K]^T  (+bias)(+gelu|+res),  A,Bt fp16, accum fp32
// CTA tile 128x256x64, 512 threads (16 warps, warp tile 32x64), 4-stage cp.async
// ============================================================================
#define BM 128
#define BN 256
#define BK 64                     // fp16 elements per k-chunk (128 B)
#define ROWB 144                  // padded smem row pitch in bytes (128 + 16)
#define A_BYTES (BM*ROWB)         // 18432
#define B_BYTES (BN*ROWB)         // 36864
#define STG (A_BYTES + B_BYTES)   // 55296
#define NST 4
#define HG_SMEM (NST*STG)         // 221184

#define EPI_NONE 0
#define EPI_BIAS 1
#define EPI_GELU 2
#define EPI_RES  3

template<int EPI, bool OUT_HALF>
__global__ void __launch_bounds__(512, 1)
hgemm(const __half* __restrict__ A, int lda,
      const __half* __restrict__ Bt, int ldb,     // Bt: [N,K]
      const float* __restrict__ bias,
      const __half* __restrict__ resh, int ldres, // residual (fp16) for EPI_RES
      void* __restrict__ Cv, int ldc,
      int M, int N, int K)
{
    extern __shared__ char sm[];
    const unsigned smb = smem_u32(sm);
    const int tid  = threadIdx.x;
    const int lane = tid & 31;
    const int wid  = tid >> 5;
    const int bm0 = blockIdx.y * BM;
    const int bn0 = blockIdx.x * BN;
    const int wm = (wid & 3) * 32;        // warp tile origin (m)
    const int wn = (wid >> 2) * 64;       // warp tile origin (n)

    // per-lane ldmatrix offsets (bytes, within a 16x16 / 16n x 16k tile)
    const unsigned aoff = (unsigned)(((lane & 7) + ((lane >> 3) & 1) * 8) * ROWB
                                     + (lane >> 4) * 16);
    const unsigned boff = (unsigned)(((lane & 7) + (lane >> 4) * 8) * ROWB
                                     + ((lane >> 3) & 1) * 16);

    // --- stage loader ---
    const int lrow = tid >> 3;            // 0..63
    const int lchk = tid & 7;             // 16B chunk within 128B row
    auto load_stage = [&](int s, int kt) {
        const int k0 = kt * BK;
        const unsigned abase = smb + s * STG;
        #pragma unroll
        for (int i = 0; i < 2; i++) {
            const int r = lrow + 64 * i;
            const unsigned d = abase + (unsigned)(r * ROWB + lchk * 16);
            const __half* g = A + (size_t)(bm0 + r) * lda + k0 + lchk * 8;
            asm volatile("cp.async.cg.shared.global [%0], [%1], 16;" :: "r"(d), "l"(g));
        }
        const unsigned bbase = abase + A_BYTES;
        #pragma unroll
        for (int i = 0; i < 4; i++) {
            const int r = lrow + 64 * i;
            const unsigned d = bbase + (unsigned)(r * ROWB + lchk * 16);
            const __half* g = Bt + (size_t)(bn0 + r) * ldb + k0 + lchk * 8;
            asm volatile("cp.async.cg.shared.global [%0], [%1], 16;" :: "r"(d), "l"(g));
        }
    };

    float acc[2][8][4];
    #pragma unroll
    for (int mt = 0; mt < 2; mt++)
        #pragma unroll
        for (int nt = 0; nt < 8; nt++)
            #pragma unroll
            for (int r = 0; r < 4; r++) acc[mt][nt][r] = 0.0f;

    const int kiters = K / BK;
    load_stage(0, 0); asm volatile("cp.async.commit_group;" ::: "memory");
    load_stage(1, 1); asm volatile("cp.async.commit_group;" ::: "memory");
    load_stage(2, 2); asm volatile("cp.async.commit_group;" ::: "memory");

    for (int kt = 0; kt < kiters; kt++) {
        const int s = kt & 3;
        asm volatile("cp.async.wait_group 2;" ::: "memory");
        __syncthreads();

        const unsigned abase = smb + s * STG + (unsigned)(wm * ROWB) + aoff;
        const unsigned bbase = smb + s * STG + A_BYTES + (unsigned)(wn * ROWB) + boff;

        #pragma unroll
        for (int k16 = 0; k16 < 4; k16++) {
            uint32_t af[2][4];
            #pragma unroll
            for (int mt = 0; mt < 2; mt++) {
                const unsigned addr = abase + (unsigned)(mt * 16 * ROWB + k16 * 32);
                asm volatile("ldmatrix.sync.aligned.m8n8.x4.shared.b16 {%0,%1,%2,%3}, [%4];"
                             : "=r"(af[mt][0]), "=r"(af[mt][1]),
                               "=r"(af[mt][2]), "=r"(af[mt][3]) : "r"(addr));
            }
            uint32_t bf[4][4];
            #pragma unroll
            for (int np = 0; np < 4; np++) {
                const unsigned addr = bbase + (unsigned)(np * 16 * ROWB + k16 * 32);
                asm volatile("ldmatrix.sync.aligned.m8n8.x4.shared.b16 {%0,%1,%2,%3}, [%4];"
                             : "=r"(bf[np][0]), "=r"(bf[np][1]),
                               "=r"(bf[np][2]), "=r"(bf[np][3]) : "r"(addr));
            }
            #pragma unroll
            for (int mt = 0; mt < 2; mt++)
                #pragma unroll
                for (int np = 0; np < 4; np++) {
                    asm volatile(
                        "mma.sync.aligned.m16n8k16.row.col.f32.f16.f16.f32 "
                        "{%0,%1,%2,%3}, {%4,%5,%6,%7}, {%8,%9}, {%0,%1,%2,%3};"
                        : "+f"(acc[mt][2*np][0]), "+f"(acc[mt][2*np][1]),
                          "+f"(acc[mt][2*np][2]), "+f"(acc[mt][2*np][3])
                        : "r"(af[mt][0]), "r"(af[mt][1]), "r"(af[mt][2]), "r"(af[mt][3]),
                          "r"(bf[np][0]), "r"(bf[np][1]));
                    asm volatile(
                        "mma.sync.aligned.m16n8k16.row.col.f32.f16.f16.f32 "
                        "{%0,%1,%2,%3}, {%4,%5,%6,%7}, {%8,%9}, {%0,%1,%2,%3};"
                        : "+f"(acc[mt][2*np+1][0]), "+f"(acc[mt][2*np+1][1]),
                          "+f"(acc[mt][2*np+1][2]), "+f"(acc[mt][2*np+1][3])
                        : "r"(af[mt][0]), "r"(af[mt][1]), "r"(af[mt][2]), "r"(af[mt][3]),
                          "r"(bf[np][2]), "r"(bf[np][3]));
                }
        }

        if (kt + 3 < kiters) load_stage((kt + 3) & 3, kt + 3);
        asm volatile("cp.async.commit_group;" ::: "memory");
    }

    // --- epilogue ---
    #pragma unroll
    for (int mt = 0; mt < 2; mt++) {
        const int r0 = bm0 + wm + mt * 16 + (lane >> 2);
        const int r1 = r0 + 8;
        #pragma unroll
        for (int nt = 0; nt < 8; nt++) {
            const int c = bn0 + wn + nt * 8 + ((lane & 3) << 1);
            float2 v0 = make_float2(acc[mt][nt][0], acc[mt][nt][1]);
            float2 v1 = make_float2(acc[mt][nt][2], acc[mt][nt][3]);
            if (EPI != EPI_NONE) {
                const float bx = bias[c], by = bias[c + 1];
                v0.x += bx; v0.y += by; v1.x += bx; v1.y += by;
            }
            if (EPI == EPI_GELU) {
                v0.x = gelu_tanh(v0.x); v0.y = gelu_tanh(v0.y);
                v1.x = gelu_tanh(v1.x); v1.y = gelu_tanh(v1.y);
            }
            if (EPI == EPI_RES) {
                const __half2 ra = *(const __half2*)(resh + (size_t)r0 * ldres + c);
                const __half2 rb = *(const __half2*)(resh + (size_t)r1 * ldres + c);
                const float2 fa = __half22float2(ra), fb = __half22float2(rb);
                v0.x += fa.x; v0.y += fa.y; v1.x += fb.x; v1.y += fb.y;
            }
            if (OUT_HALF) {
                __half* C = (__half*)Cv;
                *(__half2*)(C + (size_t)r0 * ldc + c) = __floats2half2_rn(v0.x, v0.y);
                *(__half2*)(C + (size_t)r1 * ldc + c) = __floats2half2_rn(v1.x, v1.y);
            } else {
                float* C = (float*)Cv;
                *(float2*)(C + (size_t)r0 * ldc + c) = v0;
                *(float2*)(C + (size_t)r1 * ldc + c) = v1;
            }
        }
    }
}

// ---------------- small kernels --------------------------------------------

// fp32 -> fp16
__global__ void to_half_kernel(const float* __restrict__ src, __half* __restrict__ dst, int n4) {
    const int i = blockIdx.x * blockDim.x + threadIdx.x;
    if (i < n4) {
        const float4 v = ((const float4*)src)[i];
        ((__half2*)dst)[2*i]   = __floats2half2_rn(v.x, v.y);
        ((__half2*)dst)[2*i+1] = __floats2half2_rn(v.z, v.w);
    }
}

// transpose + to fp16: src[K,N] fp32 row-major -> dst[N,K] fp16 row-major
__global__ void transpose_half_kernel(const float* __restrict__ src,
                                      __half* __restrict__ dst, int K, int N) {
    __shared__ float t[32][33];
    const int tx = threadIdx.x, ty = threadIdx.y;     // 32 x 8
    const int k0 = blockIdx.y * 32, n0 = blockIdx.x * 32;
    #pragma unroll
    for (int i = 0; i < 32; i += 8)
        t[ty + i][tx] = src[(size_t)(k0 + ty + i) * N + n0 + tx];
    __syncthreads();
    #pragma unroll
    for (int i = 0; i < 32; i += 8)
        dst[(size_t)(n0 + ty + i) * K + k0 + tx] = __float2half_rn(t[tx][ty + i]);
}

// copy state [B, 8*U] into mem_plus slots 0..7 (fp16) and compact g_memr (fp16)
__global__ void copy_state_kernel(const float* __restrict__ state) {
    const int row = blockIdx.x;
    const int b = row >> 3, m = row & 7;
    const int tid = threadIdx.x;
    const float4 v = ((const float4*)(state + (size_t)row * UNITS))[tid];
    const __half2 h0 = __floats2half2_rn(v.x, v.y);
    const __half2 h1 = __floats2half2_rn(v.z, v.w);
    __half2* d0 = (__half2*)(g_memplus + ((size_t)b * SLOTS + m) * UNITS);
    __half2* d1 = (__half2*)(g_memr + (size_t)row * UNITS);
    d0[2*tid] = h0; d0[2*tid+1] = h1;
    d1[2*tid] = h0; d1[2*tid+1] = h1;
}

// rel-pos sinusoid table
__global__ void tab_kernel() {
    const int p = blockIdx.x;
    const float pos = (float)(p - MEMS);
    for (int j = threadIdx.x; j < UNITS; j += blockDim.x) {
        const float expo = (float)(j - (j & 1)) / (float)UNITS;
        const float angle = pos * __expf(-expo * 9.210340371976184f);
        g_tab[p * UNITS + j] = (j & 1) ? cosf(angle) : sinf(angle);
    }
}

// rel_emb[17,U] = tab @ rel_kernel[U,U]  (tiny, fp32 exact)
__global__ void relgemm_kernel(const float* __restrict__ rel_kernel) {
    const int p = blockIdx.y;
    const int n = blockIdx.x * blockDim.x + threadIdx.x;
    float acc = 0.0f;
    const float* tp = g_tab + p * UNITS;
    for (int j = 0; j < UNITS; j++)
        acc = fmaf(tp[j], rel_kernel[(size_t)j * UNITS + n], acc);
    g_rel[p * UNITS + n] = acc;
}

// attention per (b, h): S=9, dh=64 (fp32)
__global__ void __launch_bounds__(64) attn_kernel() {
    const int b = blockIdx.x, h = blockIdx.y;
    const int tid = threadIdx.x;

    __shared__ float q[SLOTS][DH], k[SLOTS][DH], v[SLOTS][DH];
    __shared__ float r[17][DH];
    __shared__ float sc[SLOTS * SLOTS];

    const float scale = 0.125f;
    const size_t base = ((size_t)b * SLOTS) * (3 * UNITS) + (size_t)h * DH;

    for (int i = tid; i < SLOTS * DH; i += 64) {
        const int s = i >> 6, d = i & 63;
        const size_t o = base + (size_t)s * (3 * UNITS) + d;
        q[s][d] = g_qkv[o] * scale;
        k[s][d] = g_qkv[o + UNITS];
        v[s][d] = g_qkv[o + 2 * UNITS];
    }
    for (int i = tid; i < 17 * DH; i += 64) {
        const int p = i >> 6, d = i & 63;
        r[p][d] = g_rel[p * UNITS + h * DH + d];
    }
    __syncthreads();

    for (int p = tid; p < SLOTS * SLOTS; p += 64) {
        const int qi = p / SLOTS, ki = p % SLOTS;
        const float* rr = r[qi - ki + MEMS];
        float acc = 0.0f;
        #pragma unroll 16
        for (int d = 0; d < DH; d++)
            acc = fmaf(q[qi][d], k[ki][d] + rr[d], acc);
        sc[p] = acc;
    }
    __syncthreads();

    if (tid < SLOTS) {
        float mx = -1e30f;
        #pragma unroll
        for (int j = 0; j < SLOTS; j++) mx = fmaxf(mx, sc[tid * SLOTS + j]);
        float e[SLOTS], sum = 0.0f;
        #pragma unroll
        for (int j = 0; j < SLOTS; j++) { e[j] = __expf(sc[tid * SLOTS + j] - mx); sum += e[j]; }
        const float inv = 1.0f / sum;
        #pragma unroll
        for (int j = 0; j < SLOTS; j++) sc[tid * SLOTS + j] = e[j] * inv;
    }
    __syncthreads();

    const int d = tid;
    #pragma unroll
    for (int qi = 0; qi < SLOTS; qi++) {
        float acc = 0.0f;
        #pragma unroll
        for (int kk = 0; kk < SLOTS; kk++)
            acc = fmaf(sc[qi * SLOTS + kk], v[kk][d], acc);
        g_att[((size_t)b * SLOTS + qi) * UNITS + h * DH + d] = acc;
    }
}

// LN1: out_h = LN(memplus_fp16 + att_fp32) -> fp16
__global__ void __launch_bounds__(256)
ln1_kernel(const float* __restrict__ gamma, const float* __restrict__ beta)
{
    const int row = blockIdx.x;
    const int tid = threadIdx.x;
    const __half2* xh = (const __half2*)(g_memplus + (size_t)row * UNITS);
    const float2 a0 = __half22float2(xh[2*tid]);
    const float2 a1 = __half22float2(xh[2*tid+1]);
    const float4 y = ((const float4*)(g_att + (size_t)row * UNITS))[tid];
    float4 x = make_float4(a0.x + y.x, a0.y + y.y, a1.x + y.z, a1.y + y.w);

    float s  = x.x + x.y + x.z + x.w;
    float ss = x.x*x.x + x.y*x.y + x.z*x.z + x.w*x.w;
    __shared__ float red[16];
    #pragma unroll
    for (int o = 16; o > 0; o >>= 1) {
        s  += __shfl_down_sync(0xffffffff, s, o);
        ss += __shfl_down_sync(0xffffffff, ss, o);
    }
    const int warp = tid >> 5, lane = tid & 31;
    if (lane == 0) { red[warp] = s; red[warp + 8] = ss; }
    __syncthreads();
    if (tid == 0) {
        float ts = 0.0f, tss = 0.0f;
        #pragma unroll
        for (int w = 0; w < 8; w++) { ts += red[w]; tss += red[w + 8]; }
        const float mean = ts * (1.0f / UNITS);
        red[0] = mean;
        red[1] = rsqrtf(tss * (1.0f / UNITS) - mean * mean + LN_EPS);
    }
    __syncthreads();
    const float mean = red[0], rstd = red[1];

    const float4 g = ((const float4*)gamma)[tid];
    const float4 bb = ((const float4*)beta)[tid];
    __half2* oh = (__half2*)(g_h + (size_t)row * UNITS);
    oh[2*tid]   = __floats2half2_rn((x.x - mean) * rstd * g.x + bb.x,
                                    (x.y - mean) * rstd * g.y + bb.y);
    oh[2*tid+1] = __floats2half2_rn((x.z - mean) * rstd * g.z + bb.z,
                                    (x.w - mean) * rstd * g.w + bb.w);
}

// LN2: h2 = LN(hm) fp32 -> fp32
__global__ void __launch_bounds__(256)
ln2_kernel(const float* __restrict__ gamma, const float* __restrict__ beta)
{
    const int row = blockIdx.x;
    const int tid = threadIdx.x;
    const float4 x = ((const float4*)(g_hm + (size_t)row * UNITS))[tid];

    float s  = x.x + x.y + x.z + x.w;
    float ss = x.x*x.x + x.y*x.y + x.z*x.z + x.w*x.w;
    __shared__ float red[16];
    #pragma unroll
    for (int o = 16; o > 0; o >>= 1) {
        s  += __shfl_down_sync(0xffffffff, s, o);
        ss += __shfl_down_sync(0xffffffff, ss, o);
    }
    const int warp = tid >> 5, lane = tid & 31;
    if (lane == 0) { red[warp] = s; red[warp + 8] = ss; }
    __syncthreads();
    if (tid == 0) {
        float ts = 0.0f, tss = 0.0f;
        #pragma unroll
        for (int w = 0; w < 8; w++) { ts += red[w]; tss += red[w + 8]; }
        const float mean = ts * (1.0f / UNITS);
        red[0] = mean;
        red[1] = rsqrtf(tss * (1.0f / UNITS) - mean * mean + LN_EPS);
    }
    __syncthreads();
    const float mean = red[0], rstd = red[1];

    const float4 g = ((const float4*)gamma)[tid];
    const float4 bb = ((const float4*)beta)[tid];
    float4 o;
    o.x = (x.x - mean) * rstd * g.x + bb.x;
    o.y = (x.y - mean) * rstd * g.y + bb.y;
    o.z = (x.z - mean) * rstd * g.z + bb.z;
    o.w = (x.w - mean) * rstd * g.w + bb.w;
    ((float4*)(g_h2 + (size_t)row * UNITS))[tid] = o;
}

// copy output rows h2[:, M, :] -> out[0 : B*U]
__global__ void outcopy_kernel(float* __restrict__ out) {
    const int b = blockIdx.x;
    const float4* src = (const float4*)(g_h2 + ((size_t)b * SLOTS + MEMS) * UNITS);
    ((float4*)(out + (size_t)b * UNITS))[threadIdx.x] = src[threadIdx.x];
}

// gates + next_memory
__global__ void __launch_bounds__(256)
gates_kernel(const float* __restrict__ state, float* __restrict__ out)
{
    const int row = blockIdx.x;
    const int b = row >> 3, m = row & 7;
    const int tid = threadIdx.x;

    const float4 g0i = ((const float4*)(g_g0 + (size_t)b * 2 * UNITS))[tid];
    const float4 g0f = ((const float4*)(g_g0 + (size_t)b * 2 * UNITS + UNITS))[tid];
    const float4 g1i = ((const float4*)(g_g1 + (size_t)row * 2 * UNITS))[tid];
    const float4 g1f = ((const float4*)(g_g1 + (size_t)row * 2 * UNITS + UNITS))[tid];
    const float4 mem = ((const float4*)(state + (size_t)row * UNITS))[tid];
    const float4 nm  = ((const float4*)(g_h2 + ((size_t)b * SLOTS + m) * UNITS))[tid];

    float4 o;
    o.x = hsig(g0f.x + g1f.x + 1.0f) * mem.x + hsig(g0i.x + g1i.x) * tanhf(nm.x);
    o.y = hsig(g0f.y + g1f.y + 1.0f) * mem.y + hsig(g0i.y + g1i.y) * tanhf(nm.y);
    o.z = hsig(g0f.z + g1f.z + 1.0f) * mem.z + hsig(g0i.z + g1i.z) * tanhf(nm.z);
    o.w = hsig(g0f.w + g1f.w + 1.0f) * mem.w + hsig(g0i.w + g1i.w) * tanhf(nm.w);
    ((float4*)(out + (size_t)BATCH * UNITS + (size_t)row * UNITS))[tid] = o;
}

// ---------------- host launcher ---------------------------------------------
extern "C" void kernel_launch(void* const* d_in, const int* in_sizes, int n_in,
                              void* d_out, int out_size)
{
    const float* inputs           = (const float*)d_in[0];
    const float* state            = (const float*)d_in[1];
    const float* input_kernel     = (const float*)d_in[2];
    const float* input_bias_w     = (const float*)d_in[3];
    const float* gate_kernel      = (const float*)d_in[4];
    const float* recurrent_kernel = (const float*)d_in[5];
    const float* recurrent_bias   = (const float*)d_in[6];
    const float* attention_kernel = (const float*)d_in[7];
    const float* attention_bias   = (const float*)d_in[8];
    const float* mlp_kernel       = (const float*)d_in[9];
    const float* mlp_bias         = (const float*)d_in[10];
    const float* ln_gamma         = (const float*)d_in[11];
    const float* ln_beta          = (const float*)d_in[12];
    const float* rel_kernel       = (const float*)d_in[13];
    float* out = (float*)d_out;

    static __half *p_memplus = nullptr, *p_h, *p_t, *p_xr, *p_memr,
                  *p_wtin, *p_wtgate, *p_wtrec, *p_wtatt, *p_wtmlp;
    static float *p_qkv, *p_hm, *p_g0, *p_g1;
    static bool init_done = false;
    if (!init_done) {
        cudaGetSymbolAddress((void**)&p_memplus, g_memplus);
        cudaGetSymbolAddress((void**)&p_h, g_h);
        cudaGetSymbolAddress((void**)&p_t, g_t);
        cudaGetSymbolAddress((void**)&p_xr, g_xr);
        cudaGetSymbolAddress((void**)&p_memr, g_memr);
        cudaGetSymbolAddress((void**)&p_wtin, wt_in);
        cudaGetSymbolAddress((void**)&p_wtgate, wt_gate);
        cudaGetSymbolAddress((void**)&p_wtrec, wt_rec);
        cudaGetSymbolAddress((void**)&p_wtatt, wt_att);
        cudaGetSymbolAddress((void**)&p_wtmlp, wt_mlp);
        cudaGetSymbolAddress((void**)&p_qkv, g_qkv);
        cudaGetSymbolAddress((void**)&p_hm, g_hm);
        cudaGetSymbolAddress((void**)&p_g0, g_g0);
        cudaGetSymbolAddress((void**)&p_g1, g_g1);

        cudaFuncSetAttribute(hgemm<EPI_BIAS, true >, cudaFuncAttributeMaxDynamicSharedMemorySize, HG_SMEM);
        cudaFuncSetAttribute(hgemm<EPI_BIAS, false>, cudaFuncAttributeMaxDynamicSharedMemorySize, HG_SMEM);
        cudaFuncSetAttribute(hgemm<EPI_GELU, true >, cudaFuncAttributeMaxDynamicSharedMemorySize, HG_SMEM);
        cudaFuncSetAttribute(hgemm<EPI_RES,  false>, cudaFuncAttributeMaxDynamicSharedMemorySize, HG_SMEM);
        cudaFuncSetAttribute(hgemm<EPI_NONE, false>, cudaFuncAttributeMaxDynamicSharedMemorySize, HG_SMEM);
        init_done = true;
    }

    const dim3 tb(32, 8);

    // --- convert inputs; transpose+convert weights to [N,K] fp16 ---
    to_half_kernel<<<(BATCH*DIMD/4 + 255)/256, 256>>>(inputs, p_xr, BATCH*DIMD/4);
    transpose_half_kernel<<<dim3(UNITS/32,   DIMD/32),  tb>>>(input_kernel,     p_wtin,   DIMD,  UNITS);
    transpose_half_kernel<<<dim3(2*UNITS/32, DIMD/32),  tb>>>(gate_kernel,      p_wtgate, DIMD,  2*UNITS);
    transpose_half_kernel<<<dim3(2*UNITS/32, UNITS/32), tb>>>(recurrent_kernel, p_wtrec,  UNITS, 2*UNITS);
    transpose_half_kernel<<<dim3(3*UNITS/32, UNITS/32), tb>>>(attention_kernel, p_wtatt,  UNITS, 3*UNITS);
    transpose_half_kernel<<<dim3(2*UNITS/32, UNITS/32), tb>>>(mlp_kernel,       p_wtmlp,  UNITS, 2*UNITS);

    // rel-pos table + tiny GEMM
    tab_kernel<<<17, 256>>>();
    relgemm_kernel<<<dim3(UNITS / 256, 17), 256>>>(rel_kernel);

    // mem_plus: state slots (fp16) + x = inputs @ Wi + bi (slot 8, fp16)
    copy_state_kernel<<<GROWS, 256>>>(state);
    hgemm<EPI_BIAS, true><<<dim3(UNITS/BN, BATCH/BM), 512, HG_SMEM>>>(
        p_xr, DIMD, p_wtin, DIMD, input_bias_w,
        nullptr, 0, p_memplus + (size_t)MEMS * UNITS, SLOTS * UNITS,
        BATCH, UNITS, DIMD);

    // qkv = mem_plus @ Wa + ba  (fp32 out)
    hgemm<EPI_BIAS, false><<<dim3(3*UNITS/BN, ROWS/BM), 512, HG_SMEM>>>(
        p_memplus, UNITS, p_wtatt, UNITS, attention_bias,
        nullptr, 0, p_qkv, 3 * UNITS, ROWS, 3 * UNITS, UNITS);

    // attention
    attn_kernel<<<dim3(BATCH, HEADS), 64>>>();

    // h = LN(mem_plus + att)  (fp16 out)
    ln1_kernel<<<ROWS, 256>>>(ln_gamma, ln_beta);

    // t = gelu(h @ w1 + mb1)  (fp16 out)
    hgemm<EPI_GELU, true><<<dim3(UNITS/BN, ROWS/BM), 512, HG_SMEM>>>(
        p_h, UNITS, p_wtmlp, UNITS, mlp_bias,
        nullptr, 0, p_t, UNITS, ROWS, UNITS, UNITS);

    // hm = h + (t @ w2 + mb2)  (fp32 out)
    hgemm<EPI_RES, false><<<dim3(UNITS/BN, ROWS/BM), 512, HG_SMEM>>>(
        p_t, UNITS, p_wtmlp + (size_t)UNITS * UNITS, UNITS, mlp_bias + UNITS,
        p_h, UNITS, p_hm, UNITS, ROWS, UNITS, UNITS);

    // h2 = LN(hm)
    ln2_kernel<<<ROWS, 256>>>(ln_gamma + UNITS, ln_beta + UNITS);

    // gates
    hgemm<EPI_NONE, false><<<dim3(2*UNITS/BN, BATCH/BM), 512, HG_SMEM>>>(
        p_xr, DIMD, p_wtgate, DIMD, nullptr,
        nullptr, 0, p_g0, 2 * UNITS, BATCH, 2 * UNITS, DIMD);
    hgemm<EPI_BIAS, false><<<dim3(2*UNITS/BN, GROWS/BM), 512, HG_SMEM>>>(
        p_memr, UNITS, p_wtrec, UNITS, recurrent_bias,
        nullptr, 0, p_g1, 2 * UNITS, GROWS, 2 * UNITS, UNITS);

    // outputs
    outcopy_kernel<<<BATCH, 256>>>(out);
    gates_kernel<<<GROWS, 256>>>(state, out);
}